// round 9
// baseline (speedup 1.0000x reference)
#include <cuda_runtime.h>
#include <cstdint>

// Problem constants
#define BATCH   256
#define N0      4096
#define N1      4096
#define N2      4096
#define N3      1024

#define ROWS_PER_BLOCK 8
#define NB_W1 (N0 / ROWS_PER_BLOCK)
#define NB_W2 (N1 / ROWS_PER_BLOCK)
#define NB_W3 (N2 / ROWS_PER_BLOCK)

#define GROUPS  128   // batch groups of 2 (2x16-bit fields per u32)

// Routing tables as u16 (indices < 4096), 16B-aligned for uint4 staging.
__device__ __align__(16) unsigned short g_d1[N0];
__device__ __align__(16) unsigned short g_d2[N1];
__device__ __align__(16) unsigned short g_d3[N2];

// ---------------------------------------------------------------------------
// Cluster helpers
// ---------------------------------------------------------------------------
__device__ __forceinline__ uint32_t smem_u32(const void* p) {
    uint32_t a;
    asm("{ .reg .u64 t; cvta.to.shared.u64 t, %1; cvt.u32.u64 %0, t; }"
        : "=r"(a) : "l"(p));
    return a;
}
__device__ __forceinline__ uint32_t cluster_rank() {
    uint32_t r; asm("mov.u32 %0, %%cluster_ctarank;" : "=r"(r)); return r;
}
__device__ __forceinline__ uint32_t mapa_shared(uint32_t addr, uint32_t rank) {
    uint32_t r;
    asm("mapa.shared::cluster.u32 %0, %1, %2;" : "=r"(r) : "r"(addr), "r"(rank));
    return r;
}
__device__ __forceinline__ unsigned ld_shared_cluster_u32(uint32_t addr) {
    unsigned v;
    asm volatile("ld.shared::cluster.u32 %0, [%1];" : "=r"(v) : "r"(addr));
    return v;
}
#define CLUSTER_SYNC() do { \
    asm volatile("barrier.cluster.arrive.aligned;" ::: "memory"); \
    asm volatile("barrier.cluster.wait.aligned;"   ::: "memory"); \
} while (0)

// ---------------------------------------------------------------------------
// Row argmax — FROZEN round-3 configuration (measured 25.9-26.2us, DRAM ~75%).
// Warp per row, 8x-unrolled float4 loads. First-occurrence (jnp.argmax).
// ---------------------------------------------------------------------------
__device__ __forceinline__ void argmax_row(const float* __restrict__ W,
                                           int row, int n_cols, int lane,
                                           unsigned short* __restrict__ out_idx)
{
    const float4* __restrict__ Wr =
        reinterpret_cast<const float4*>(W + (size_t)row * n_cols);
    const int n4 = n_cols >> 2;

    float best = -__int_as_float(0x7f800000);  // -inf
    int   bidx = 0;

    for (int i = lane; i < n4; i += 256) {
        float4 v[8];
        #pragma unroll
        for (int u = 0; u < 8; ++u) v[u] = Wr[i + u * 32];

        float g = -__int_as_float(0x7f800000);
        #pragma unroll
        for (int u = 0; u < 8; ++u)
            g = fmaxf(g, fmaxf(fmaxf(v[u].x, v[u].y), fmaxf(v[u].z, v[u].w)));

        if (g > best) {
            best = g;
            int idx = 0;
            // descending scan: last surviving write = smallest matching index
            #pragma unroll
            for (int u = 7; u >= 0; --u) {
                int base = (i + u * 32) << 2;
                if (v[u].w == g) idx = base + 3;
                if (v[u].z == g) idx = base + 2;
                if (v[u].y == g) idx = base + 1;
                if (v[u].x == g) idx = base;
            }
            bidx = idx;
        }
    }

    #pragma unroll
    for (int off = 16; off > 0; off >>= 1) {
        float ov = __shfl_down_sync(0xffffffffu, best, off);
        int   oi = __shfl_down_sync(0xffffffffu, bidx, off);
        if (ov > best || (ov == best && oi < bidx)) { best = ov; bidx = oi; }
    }
    if (lane == 0) out_idx[row] = (unsigned short)bidx;
}

__global__ void __launch_bounds__(256) fused_argmax_kernel(
    const float* __restrict__ W1,
    const float* __restrict__ W2,
    const float* __restrict__ W3)
{
    const int warp = threadIdx.x >> 5;
    const int lane = threadIdx.x & 31;
    const int bid  = blockIdx.x;

    if (bid < NB_W1) {
        argmax_row(W1, bid * ROWS_PER_BLOCK + warp, N1, lane, g_d1);
    } else if (bid < NB_W1 + NB_W2) {
        argmax_row(W2, (bid - NB_W1) * ROWS_PER_BLOCK + warp, N2, lane, g_d2);
    } else {
        argmax_row(W3, (bid - NB_W1 - NB_W2) * ROWS_PER_BLOCK + warp, N3, lane, g_d3);
    }
}

// ---------------------------------------------------------------------------
// Scatter: 2-CTA clusters. Cluster c handles batches {2c, 2c+1} (u32-packed:
// counts 0..7, per-bin totals <= 28672 < 2^16 -> fields never carry).
// Rank r processes sources [2048r, 2048r+2048) -> 2048 smem atomic lane-ops
// per CTA (HALF the per-SM LSU atomic work of the single-CTA version).
// barrier.cluster (release/acquire) then rank 0 merges rank 1's 4KB histogram
// over DSMEM and writes both output rows. No global scratch, no fences.
// ---------------------------------------------------------------------------
__global__ void __cluster_dims__(2, 1, 1) __launch_bounds__(512)
scatter_kernel(const int* __restrict__ x, float* __restrict__ out)
{
    __shared__ unsigned short t1[N0];
    __shared__ unsigned short t2[N1];
    __shared__ unsigned short t3[N2];
    __shared__ unsigned int hist[N3];

    const int tid  = threadIdx.x;
    const int g    = blockIdx.x >> 1;        // group = cluster id
    const uint32_t rank = cluster_rank();    // 0 or 1

    // Stage tables: 3 x 512 uint4 over 512 threads (3 loads each).
    reinterpret_cast<uint4*>(t1)[tid] = reinterpret_cast<const uint4*>(g_d1)[tid];
    reinterpret_cast<uint4*>(t2)[tid] = reinterpret_cast<const uint4*>(g_d2)[tid];
    reinterpret_cast<uint4*>(t3)[tid] = reinterpret_cast<const uint4*>(g_d3)[tid];
    hist[tid]       = 0u;
    hist[tid + 512] = 0u;
    __syncthreads();

    const int* __restrict__ xa = x + (size_t)(2 * g)     * N0;
    const int* __restrict__ xb = x + (size_t)(2 * g + 1) * N0;

    // This CTA's half of the sources: 4 consecutive per thread.
    const int s0 = (int)rank * (N0 / 2) + 4 * tid;
    int4 c0 = *reinterpret_cast<const int4*>(xa + s0);
    int4 c1 = *reinterpret_cast<const int4*>(xb + s0);

    // 4 independent 3-hop LDS compose chains
    int f0 = t3[t2[t1[s0]]];
    int f1 = t3[t2[t1[s0 + 1]]];
    int f2 = t3[t2[t1[s0 + 2]]];
    int f3 = t3[t2[t1[s0 + 3]]];

    unsigned v0 = (unsigned)c0.x | ((unsigned)c1.x << 16);
    unsigned v1 = (unsigned)c0.y | ((unsigned)c1.y << 16);
    unsigned v2 = (unsigned)c0.z | ((unsigned)c1.z << 16);
    unsigned v3 = (unsigned)c0.w | ((unsigned)c1.w << 16);

    if (v0) atomicAdd(&hist[f0], v0);
    if (v1) atomicAdd(&hist[f1], v1);
    if (v2) atomicAdd(&hist[f2], v2);
    if (v3) atomicAdd(&hist[f3], v3);

    __syncthreads();

    // Both CTAs' histograms complete & visible cluster-wide.
    CLUSTER_SYNC();

    if (rank == 0) {
        // Merge peer histogram over DSMEM and write both output rows.
        const uint32_t local  = smem_u32(hist);
        const uint32_t remote = mapa_shared(local, 1);

        float* __restrict__ oa = out + (size_t)(2 * g)     * N3;
        float* __restrict__ ob = out + (size_t)(2 * g + 1) * N3;

        #pragma unroll
        for (int half = 0; half < 2; ++half) {
            int j = tid + half * 512;
            unsigned v = hist[j] + ld_shared_cluster_u32(remote + 4u * j);
            oa[j] = (float)(v & 0xFFFFu);
            ob[j] = (float)(v >> 16);
        }
    }

    // Keep rank 1 alive until rank 0 finished reading its smem.
    CLUSTER_SYNC();
}

// ---------------------------------------------------------------------------
// Launch
//   d_in[0] = x  (int32,   [256, 4096])
//   d_in[1] = W1 (float32, [4096, 4096])
//   d_in[2] = W2 (float32, [4096, 4096])
//   d_in[3] = W3 (float32, [4096, 1024])
//   d_out   = float32 [256, 1024]
// ---------------------------------------------------------------------------
extern "C" void kernel_launch(void* const* d_in, const int* in_sizes, int n_in,
                              void* d_out, int out_size)
{
    const int*   x  = (const int*)  d_in[0];
    const float* W1 = (const float*)d_in[1];
    const float* W2 = (const float*)d_in[2];
    const float* W3 = (const float*)d_in[3];
    float* out = (float*)d_out;

    fused_argmax_kernel<<<NB_W1 + NB_W2 + NB_W3, 256>>>(W1, W2, W3);
    scatter_kernel<<<GROUPS * 2, 512>>>(x, out);
}

// round 10
// speedup vs baseline: 1.0714x; 1.0714x over previous
#include <cuda_runtime.h>
#include <cstdint>

// Problem constants
#define BATCH   256
#define N0      4096
#define N1      4096
#define N2      4096
#define N3      1024

#define ROWS_PER_BLOCK 8
#define NB_W1 (N0 / ROWS_PER_BLOCK)
#define NB_W2 (N1 / ROWS_PER_BLOCK)
#define NB_W3 (N2 / ROWS_PER_BLOCK)

#define GROUPS  128   // batch groups of 2 (2x16-bit fields per u32)

// Routing tables as u16 (indices < 4096), 16B-aligned for uint4 staging.
__device__ __align__(16) unsigned short g_d1[N0];
__device__ __align__(16) unsigned short g_d2[N1];
__device__ __align__(16) unsigned short g_d3[N2];

// ---------------------------------------------------------------------------
// Row argmax — round-3 body (measured 25.9us, DRAM 75%) with ONE change:
// __ldcs streaming loads (W has zero reuse; stop thrashing L2).
// Warp per row, 8x-unrolled float4 loads. First-occurrence (jnp.argmax).
// ---------------------------------------------------------------------------
__device__ __forceinline__ void argmax_row(const float* __restrict__ W,
                                           int row, int n_cols, int lane,
                                           unsigned short* __restrict__ out_idx)
{
    const float4* __restrict__ Wr =
        reinterpret_cast<const float4*>(W + (size_t)row * n_cols);
    const int n4 = n_cols >> 2;

    float best = -__int_as_float(0x7f800000);  // -inf
    int   bidx = 0;

    for (int i = lane; i < n4; i += 256) {
        float4 v[8];
        #pragma unroll
        for (int u = 0; u < 8; ++u) v[u] = __ldcs(&Wr[i + u * 32]);

        float g = -__int_as_float(0x7f800000);
        #pragma unroll
        for (int u = 0; u < 8; ++u)
            g = fmaxf(g, fmaxf(fmaxf(v[u].x, v[u].y), fmaxf(v[u].z, v[u].w)));

        if (g > best) {
            best = g;
            int idx = 0;
            // descending scan: last surviving write = smallest matching index
            #pragma unroll
            for (int u = 7; u >= 0; --u) {
                int base = (i + u * 32) << 2;
                if (v[u].w == g) idx = base + 3;
                if (v[u].z == g) idx = base + 2;
                if (v[u].y == g) idx = base + 1;
                if (v[u].x == g) idx = base;
            }
            bidx = idx;
        }
    }

    #pragma unroll
    for (int off = 16; off > 0; off >>= 1) {
        float ov = __shfl_down_sync(0xffffffffu, best, off);
        int   oi = __shfl_down_sync(0xffffffffu, bidx, off);
        if (ov > best || (ov == best && oi < bidx)) { best = ov; bidx = oi; }
    }
    if (lane == 0) out_idx[row] = (unsigned short)bidx;
}

__global__ void __launch_bounds__(256) fused_argmax_kernel(
    const float* __restrict__ W1,
    const float* __restrict__ W2,
    const float* __restrict__ W3)
{
    const int warp = threadIdx.x >> 5;
    const int lane = threadIdx.x & 31;
    const int bid  = blockIdx.x;

    if (bid < NB_W1) {
        argmax_row(W1, bid * ROWS_PER_BLOCK + warp, N1, lane, g_d1);
    } else if (bid < NB_W1 + NB_W2) {
        argmax_row(W2, (bid - NB_W1) * ROWS_PER_BLOCK + warp, N2, lane, g_d2);
    } else {
        argmax_row(W3, (bid - NB_W1 - NB_W2) * ROWS_PER_BLOCK + warp, N3, lane, g_d3);
    }
}

// ---------------------------------------------------------------------------
// Scatter — FROZEN round-8 configuration (measured 6.11us).
// Block g handles batches {2g, 2g+1}: counts pack into the two 16-bit fields
// of one u32 (counts 0..7; per-bin totals <= 4096*7 = 28672 < 2^16 -> fields
// never carry). 1024 threads/block, two sub-histograms (one per half of the
// warps), merged at writeout. 128 blocks = single wave.
// ---------------------------------------------------------------------------
__global__ void __launch_bounds__(1024) scatter_kernel(const int* __restrict__ x,
                                                       float* __restrict__ out)
{
    __shared__ unsigned short t1[N0];
    __shared__ unsigned short t2[N1];
    __shared__ unsigned short t3[N2];
    __shared__ unsigned int hist[2][N3];

    const int tid = threadIdx.x;
    const int g   = blockIdx.x;

    // Stage tables: 3 x 512 uint4 over 1024 threads.
    if (tid < 512) {
        reinterpret_cast<uint4*>(t1)[tid] = reinterpret_cast<const uint4*>(g_d1)[tid];
        reinterpret_cast<uint4*>(t3)[tid] = reinterpret_cast<const uint4*>(g_d3)[tid];
    } else {
        reinterpret_cast<uint4*>(t2)[tid - 512] =
            reinterpret_cast<const uint4*>(g_d2)[tid - 512];
    }
    hist[0][tid & (N3 - 1)] = 0u;
    hist[1][tid & (N3 - 1)] = 0u;
    __syncthreads();

    const int* __restrict__ xa = x + (size_t)(2 * g)     * N0;
    const int* __restrict__ xb = x + (size_t)(2 * g + 1) * N0;

    // 4 consecutive sources x 2 batches per thread (one int4 per batch row).
    const int s0 = 4 * tid;
    int4 c0 = *reinterpret_cast<const int4*>(xa + s0);
    int4 c1 = *reinterpret_cast<const int4*>(xb + s0);

    // 4 independent 3-hop LDS compose chains
    int f0 = t3[t2[t1[s0]]];
    int f1 = t3[t2[t1[s0 + 1]]];
    int f2 = t3[t2[t1[s0 + 2]]];
    int f3 = t3[t2[t1[s0 + 3]]];

    unsigned v0 = (unsigned)c0.x | ((unsigned)c1.x << 16);
    unsigned v1 = (unsigned)c0.y | ((unsigned)c1.y << 16);
    unsigned v2 = (unsigned)c0.z | ((unsigned)c1.z << 16);
    unsigned v3 = (unsigned)c0.w | ((unsigned)c1.w << 16);

    unsigned int* h = hist[(tid >> 9) & 1];  // warps 0-15 -> copy 0, 16-31 -> 1
    if (v0) atomicAdd(&h[f0], v0);
    if (v1) atomicAdd(&h[f1], v1);
    if (v2) atomicAdd(&h[f2], v2);
    if (v3) atomicAdd(&h[f3], v3);

    __syncthreads();

    // Merge sub-histograms + unpack to the two output rows.
    float* __restrict__ oa = out + (size_t)(2 * g)     * N3;
    float* __restrict__ ob = out + (size_t)(2 * g + 1) * N3;
    unsigned v = hist[0][tid] + hist[1][tid];
    oa[tid] = (float)(v & 0xFFFFu);
    ob[tid] = (float)(v >> 16);
}

// ---------------------------------------------------------------------------
// Launch
//   d_in[0] = x  (int32,   [256, 4096])
//   d_in[1] = W1 (float32, [4096, 4096])
//   d_in[2] = W2 (float32, [4096, 4096])
//   d_in[3] = W3 (float32, [4096, 1024])
//   d_out   = float32 [256, 1024]
// ---------------------------------------------------------------------------
extern "C" void kernel_launch(void* const* d_in, const int* in_sizes, int n_in,
                              void* d_out, int out_size)
{
    const int*   x  = (const int*)  d_in[0];
    const float* W1 = (const float*)d_in[1];
    const float* W2 = (const float*)d_in[2];
    const float* W3 = (const float*)d_in[3];
    float* out = (float*)d_out;

    fused_argmax_kernel<<<NB_W1 + NB_W2 + NB_W3, 256>>>(W1, W2, W3);
    scatter_kernel<<<GROUPS, 1024>>>(x, out);
}